// round 4
// baseline (speedup 1.0000x reference)
#include <cuda_runtime.h>

// FwFM second-order: out[i] = sum_{k<l} S[k,l] * x[k,i] * x[l,i],  S = (W+W^T)/2.
// E=4 elems/thread (two f32x2 chains). Triangle split into 3 phases so at most
// ~20 fields are register-resident -> higher occupancy than monolithic v[39].

#define KF 39
#define NH1 20                     // fields [0,20)
#define NH2 19                     // fields [20,39)
#define NELEM (8192 * 64)
#define NQUAD (NELEM / 4)          // 131072 quads per field
#define THREADS 128

typedef unsigned long long ull;

__device__ __forceinline__ ull fma2(ull a, ull b, ull c) {
    ull d;
    asm("fma.rn.f32x2 %0, %1, %2, %3;" : "=l"(d) : "l"(a), "l"(b), "l"(c));
    return d;
}

__device__ __forceinline__ ull dup2(float s) {
    ull d;
    asm("mov.b64 %0, {%1, %1};" : "=l"(d) : "f"(s));
    return d;
}

__global__ __launch_bounds__(THREADS, 4)
void fwfm_kernel(const float* __restrict__ x,
                 const float* __restrict__ W,
                 float* __restrict__ out) {
    __shared__ float Ssh[KF * KF];

    for (int t = threadIdx.x; t < KF * KF; t += THREADS) {
        int r = t / KF;
        int c = t - r * KF;
        Ssh[t] = 0.5f * (W[r * KF + c] + W[c * KF + r]);
    }
    __syncthreads();

    const int i = blockIdx.x * THREADS + threadIdx.x;   // quad index
    const ulonglong2* __restrict__ xp = reinterpret_cast<const ulonglong2*>(x);

    ull y0 = 0ull, y1 = 0ull;

    // ---- Phase 1: load H1, triangle over H1 (190 pairs) ----
    ull a[NH1], b[NH1];
#pragma unroll
    for (int k = 0; k < NH1; ++k) {
        ulonglong2 q = xp[(size_t)k * NQUAD + i];
        a[k] = q.x;
        b[k] = q.y;
    }
#pragma unroll
    for (int l = 1; l < NH1; ++l) {
        ull t0 = 0ull, t1 = 0ull;
#pragma unroll
        for (int k = 0; k < l; ++k) {
            ull sd = dup2(Ssh[l * KF + k]);
            t0 = fma2(sd, a[k], t0);
            t1 = fma2(sd, b[k], t1);
        }
        y0 = fma2(a[l], t0, y0);
        y1 = fma2(b[l], t1, y1);
    }

    // ---- Phase 2: stream l in H2 against resident H1 (380 pairs) ----
#pragma unroll
    for (int l = NH1; l < KF; ++l) {
        ulonglong2 q = xp[(size_t)l * NQUAD + i];   // cold load; fills L1
        ull t0 = 0ull, t1 = 0ull;
#pragma unroll
        for (int k = 0; k < NH1; ++k) {
            ull sd = dup2(Ssh[l * KF + k]);
            t0 = fma2(sd, a[k], t0);
            t1 = fma2(sd, b[k], t1);
        }
        y0 = fma2(q.x, t0, y0);
        y1 = fma2(q.y, t1, y1);
    }

    __syncthreads();   // phase boundary (scheduling fence; Ssh unchanged)

    // ---- Phase 3: re-load H2 (L1 hits), triangle over H2 (171 pairs) ----
    ull c[NH2], d[NH2];
#pragma unroll
    for (int k = 0; k < NH2; ++k) {
        ulonglong2 q = xp[(size_t)(NH1 + k) * NQUAD + i];
        c[k] = q.x;
        d[k] = q.y;
    }
#pragma unroll
    for (int l = 1; l < NH2; ++l) {
        ull t0 = 0ull, t1 = 0ull;
        const int lf = NH1 + l;                     // global field index
#pragma unroll
        for (int k = 0; k < l; ++k) {
            ull sd = dup2(Ssh[lf * KF + NH1 + k]);
            t0 = fma2(sd, c[k], t0);
            t1 = fma2(sd, d[k], t1);
        }
        y0 = fma2(c[l], t0, y0);
        y1 = fma2(d[l], t1, y1);
    }

    ulonglong2 r;
    r.x = y0;
    r.y = y1;
    reinterpret_cast<ulonglong2*>(out)[i] = r;      // STG.128
}

extern "C" void kernel_launch(void* const* d_in, const int* in_sizes, int n_in,
                              void* d_out, int out_size) {
    const float* x = (const float*)d_in[0];   // [39, 8192, 64] fp32
    const float* W = (const float*)d_in[1];   // [39, 39] fp32
    float* out = (float*)d_out;               // [8192, 64] fp32

    fwfm_kernel<<<NQUAD / THREADS, THREADS>>>(x, W, out);
}